// round 16
// baseline (speedup 1.0000x reference)
#include <cuda_runtime.h>
#include <cuda_fp16.h>
#include <cstdint>
#include <math.h>

#define HID 4096
#define KVD 1024
#define TOK 4096   /* B*S */
#define SEQ 2048

// ---------------- device scratch ----------------
__device__ __half g_xh[TOK * HID];
__device__ __half g_xl[TOK * HID];
__device__ __half g_Wqh[HID * HID];
__device__ __half g_Wkh[KVD * HID];
__device__ __half g_Wvh[KVD * HID];
__device__ __half g_Woh[HID * HID];
__device__ __half g_qh[TOK * HID];
__device__ __half g_kh[TOK * KVD];
__device__ __half g_vh[TOK * KVD];
__device__ __half g_ath[TOK * HID];

// ---------------- helpers ----------------
__device__ __forceinline__ uint32_t smem_u32(const void* p) {
    uint32_t a;
    asm("{ .reg .u64 t; cvta.to.shared.u64 t, %1; cvt.u32.u64 %0, t; }" : "=r"(a) : "l"(p));
    return a;
}
__device__ __forceinline__ void cp16(uint32_t dst, const void* src) {
    asm volatile("cp.async.cg.shared.global [%0], [%1], 16;\n" :: "r"(dst), "l"(src) : "memory");
}
#define CP_COMMIT() asm volatile("cp.async.commit_group;\n" ::: "memory")

#define LDSM4(r, a) \
    asm volatile("ldmatrix.sync.aligned.m8n8.x4.shared.b16 {%0,%1,%2,%3}, [%4];" \
                 : "=r"((r)[0]), "=r"((r)[1]), "=r"((r)[2]), "=r"((r)[3]) : "r"(a))
#define LDSM4T(r, a) \
    asm volatile("ldmatrix.sync.aligned.m8n8.x4.trans.shared.b16 {%0,%1,%2,%3}, [%4];" \
                 : "=r"((r)[0]), "=r"((r)[1]), "=r"((r)[2]), "=r"((r)[3]) : "r"(a))

#define MMA16816(d, a, b0, b1) \
    asm volatile("mma.sync.aligned.m16n8k16.row.col.f32.f16.f16.f32 " \
                 "{%0,%1,%2,%3}, {%4,%5,%6,%7}, {%8,%9}, {%0,%1,%2,%3};" \
                 : "+f"((d)[0]), "+f"((d)[1]), "+f"((d)[2]), "+f"((d)[3]) \
                 : "r"((a)[0]), "r"((a)[1]), "r"((a)[2]), "r"((a)[3]), "r"(b0), "r"(b1))

__device__ __forceinline__ uint32_t pack_f16x2(float hi_, float lo_) {
    __half2 h = __floats2half2_rn(lo_, hi_);
    return *(uint32_t*)&h;
}
// fast exp2 on FMA pipe (no MUFU). rel err ~2.4e-6.
__device__ __forceinline__ float exp2p(float x) {
    x = fmaxf(x, -120.f);
    int e = __float2int_rn(x);
    float f = x - (float)e;
    float p = 1.3333558e-3f;
    p = fmaf(p, f, 9.6181291e-3f);
    p = fmaf(p, f, 5.5504109e-2f);
    p = fmaf(p, f, 2.4022651e-1f);
    p = fmaf(p, f, 6.9314718e-1f);
    p = fmaf(p, f, 1.0f);
    return p * __int_as_float((uint32_t)(e + 127) << 23);
}

// -------- fused: DoRA weights (blocks 0..10239) + x split (blocks 10240..) --
__global__ __launch_bounds__(256) void dora_split(
    const float* __restrict__ Wq, const float* __restrict__ Aq,
    const float* __restrict__ Bq, const float* __restrict__ mq,
    const float* __restrict__ Wk, const float* __restrict__ Ak,
    const float* __restrict__ Bk, const float* __restrict__ mk,
    const float* __restrict__ Wv, const float* __restrict__ Av,
    const float* __restrict__ Bv, const float* __restrict__ mv,
    const float* __restrict__ Wo, const float* __restrict__ Ao,
    const float* __restrict__ Bo, const float* __restrict__ mo,
    __half* __restrict__ Wqh, __half* __restrict__ Wkh,
    __half* __restrict__ Wvh, __half* __restrict__ Woh,
    const float* __restrict__ x, __half* __restrict__ xh,
    __half* __restrict__ xl)
{
    const int bx = blockIdx.x;
    const int tid = threadIdx.x;

    if (bx >= 10240) {
        int i = (bx - 10240) * 256 + tid;
        if (i < TOK * HID / 4) {
            float4 v = ((const float4*)x)[i];
            float vv[4] = {v.x, v.y, v.z, v.w};
            size_t base = (size_t)i * 4;
#pragma unroll
            for (int e = 0; e < 4; e++) {
                __half h = __float2half_rn(vv[e]);
                xh[base + e] = h;
                xl[base + e] = __float2half_rn(vv[e] - __half2float(h));
            }
        }
        return;
    }

    const float *W, *A, *Bm, *mvec;
    __half *Whi;
    int row;
    if (bx < 4096)      { W = Wq; A = Aq; Bm = Bq; mvec = mq; Whi = Wqh; row = bx; }
    else if (bx < 5120) { W = Wk; A = Ak; Bm = Bk; mvec = mk; Whi = Wkh; row = bx - 4096; }
    else if (bx < 6144) { W = Wv; A = Av; Bm = Bv; mvec = mv; Whi = Wvh; row = bx - 5120; }
    else                { W = Wo; A = Ao; Bm = Bo; mvec = mo; Whi = Woh; row = bx - 6144; }

    float b[8];
#pragma unroll
    for (int r = 0; r < 8; r++) b[r] = 2.0f * Bm[row * 8 + r];

    const float4* Wrow = (const float4*)(W + (size_t)row * HID);
    float4 w[4];
    float ss = 0.f;
#pragma unroll
    for (int c = 0; c < 4; c++) {
        int col4 = tid + 256 * c;
        float4 wv = Wrow[col4];
#pragma unroll
        for (int r = 0; r < 8; r++) {
            float4 av = ((const float4*)(A + (size_t)r * HID))[col4];
            wv.x += b[r] * av.x; wv.y += b[r] * av.y;
            wv.z += b[r] * av.z; wv.w += b[r] * av.w;
        }
        ss += wv.x * wv.x + wv.y * wv.y + wv.z * wv.z + wv.w * wv.w;
        w[c] = wv;
    }
#pragma unroll
    for (int off = 16; off; off >>= 1)
        ss += __shfl_xor_sync(0xffffffffu, ss, off);

    __shared__ float red[8];
    __shared__ float s_scale;
    if ((tid & 31) == 0) red[tid >> 5] = ss;
    __syncthreads();
    if (tid == 0) {
        float t = 0.f;
#pragma unroll
        for (int i = 0; i < 8; i++) t += red[i];
        s_scale = mvec[row] / (sqrtf(t) + 1e-8f);
    }
    __syncthreads();
    const float sc = s_scale;
#pragma unroll
    for (int c = 0; c < 4; c++) {
        float vv[4] = {w[c].x * sc, w[c].y * sc, w[c].z * sc, w[c].w * sc};
        size_t base = (size_t)row * HID + (tid + 256 * c) * 4;
        __half2 p0 = __floats2half2_rn(vv[0], vv[1]);
        __half2 p1 = __floats2half2_rn(vv[2], vv[3]);
        *(__half2*)&Whi[base] = p0;
        *(__half2*)&Whi[base + 2] = p1;
    }
}

// ======= QKV GEMM mainloop: 128x128 CTA tile, 128 threads, K-chunk 64 =======
#define GSTR 144
#define GTILE_B (128 * GSTR)             /* 18432 */
#define QKV_STAGE (2 * GTILE_B)          /* 36864 */
#define QKV_SMEM (2 * QKV_STAGE)         /* 73728 -> 3 CTAs/SM */

__device__ __forceinline__ void hmma_loop64(
    uint32_t sb, const __half* A0, const __half* A1, const __half* Bp,
    int nch, int tid, float acc[4][8][4])
{
    const int lane = tid & 31, wid = tid >> 5;
    const int wm = wid & 1, wn = wid >> 1;
    const int K = 4096;
    const int ldr = tid >> 3;
    const int ldc = (tid & 7) * 16;

    const uint32_t a_off = (uint32_t)(wm * 64 + (lane & 15)) * GSTR + ((lane >> 4) * 16);
    const uint32_t b_off = (uint32_t)(wn * 64 + (((lane >> 4) << 3) + (lane & 7))) * GSTR
                           + (((lane >> 3) & 1) * 16);

#define LD64(buf, ch_) do { \
    uint32_t s0_ = sb + (buf) * QKV_STAGE; \
    const __half* a_ = ((ch_) < 64 ? A0 : A1) + ((ch_) & 63) * 64; \
    const __half* b_ = Bp + ((ch_) & 63) * 64; \
    const __half* gg_[2] = {a_, b_}; \
    _Pragma("unroll") \
    for (int t_ = 0; t_ < 2; t_++) { \
        uint32_t st_ = s0_ + t_ * GTILE_B; \
        _Pragma("unroll") \
        for (int p_ = 0; p_ < 8; p_++) { \
            int r_ = ldr + p_ * 16; \
            cp16(st_ + (uint32_t)r_ * GSTR + ldc, \
                 (const char*)(gg_[t_] + (size_t)r_ * K) + ldc); \
        } \
    } \
    CP_COMMIT(); \
} while (0)

    LD64(0, 0);
    for (int ch = 0; ch < nch; ch++) {
        asm volatile("cp.async.wait_group 0;\n" ::: "memory");
        __syncthreads();
        if (ch + 1 < nch) LD64((ch + 1) & 1, ch + 1);
        const uint32_t s0 = sb + (ch & 1) * QKV_STAGE;
        const uint32_t sA = s0, sB = s0 + GTILE_B;
#pragma unroll
        for (int k16 = 0; k16 < 4; k16++) {
            const uint32_t kadd = k16 * 32;
            uint32_t aa[4][4];
#pragma unroll
            for (int mb = 0; mb < 4; mb++)
                LDSM4(aa[mb], sA + a_off + mb * (16 * GSTR) + kadd);
#pragma unroll
            for (int jb = 0; jb < 4; jb++) {
                uint32_t bb[4];
                LDSM4(bb, sB + b_off + jb * (16 * GSTR) + kadd);
#pragma unroll
                for (int mb = 0; mb < 4; mb++) {
                    MMA16816(acc[mb][2 * jb], aa[mb], bb[0], bb[1]);
                    MMA16816(acc[mb][2 * jb + 1], aa[mb], bb[2], bb[3]);
                }
            }
        }
    }
#undef LD64
}

// ---------------- merged QKV projection ----------------
__global__ __launch_bounds__(128, 3) void gemm_qkv(
    const __half* __restrict__ xh, const __half* __restrict__ xl,
    const __half* __restrict__ Wqh, const __half* __restrict__ Wkh,
    const __half* __restrict__ Wvh,
    __half* __restrict__ qh, __half* __restrict__ kh, __half* __restrict__ vh)
{
    extern __shared__ char dsm[];
    const uint32_t sb = smem_u32(dsm);
    const int tid = threadIdx.x, lane = tid & 31, wid = tid >> 5;
    const int wm = wid & 1, wn = wid >> 1;
    const int bx = blockIdx.x;
    const int row0 = blockIdx.y << 7;
    const int K = 4096;

    const __half* Bp;
    __half* Oh;
    int N, col0, nch;
    if (bx < 8)       { Bp = Wkh; Oh = kh; N = KVD; col0 = bx << 7; nch = 128; }
    else if (bx < 16) { Bp = Wvh; Oh = vh; N = KVD; col0 = (bx - 8) << 7; nch = 128; }
    else              { Bp = Wqh; Oh = qh; N = HID; col0 = (bx - 16) << 7; nch = 64; }

    float acc[4][8][4] = {};
    hmma_loop64(sb, xh + (size_t)row0 * K, xl + (size_t)row0 * K,
                Bp + (size_t)col0 * K, nch, tid, acc);

#pragma unroll
    for (int mb = 0; mb < 4; mb++) {
        const int mrow = row0 + wm * 64 + mb * 16 + (lane >> 2);
#pragma unroll
        for (int jf = 0; jf < 8; jf++) {
            const int col = col0 + wn * 64 + jf * 8 + (lane & 3) * 2;
            uint32_t h01 = pack_f16x2(acc[mb][jf][1], acc[mb][jf][0]);
            uint32_t h23 = pack_f16x2(acc[mb][jf][3], acc[mb][jf][2]);
            *(uint32_t*)&Oh[(size_t)mrow * N + col] = h01;
            *(uint32_t*)&Oh[(size_t)(mrow + 8) * N + col] = h23;
        }
    }
}

// ---------------- output projection: 128x64 tile, 4 CTAs/SM ----------------
#define OBT_B (64 * GSTR)                /* 9216 */
#define OST_B (GTILE_B + OBT_B)          /* 27648 */
#define GO_SMEM (2 * OST_B)              /* 55296 */

__global__ __launch_bounds__(128, 4) void gemm_o(
    const __half* __restrict__ Ah, const __half* __restrict__ Bh,
    float* __restrict__ C)
{
    extern __shared__ char dsm[];
    const uint32_t sb = smem_u32(dsm);
    const int tid = threadIdx.x, lane = tid & 31, wid = tid >> 5;
    const int wm = wid & 1, wn = wid >> 1;
    const int row0 = blockIdx.y << 7, col0 = blockIdx.x << 6;
    const int K = 4096, N = HID;
    const int ldr = tid >> 3;
    const int ldc = (tid & 7) * 16;

    const __half* Ap = Ah + (size_t)row0 * K;
    const __half* Bp = Bh + (size_t)col0 * K;

    const uint32_t a_off = (uint32_t)(wm * 64 + (lane & 15)) * GSTR + ((lane >> 4) * 16);
    const uint32_t b_off = (uint32_t)(wn * 32 + (((lane >> 4) << 3) + (lane & 7))) * GSTR
                           + (((lane >> 3) & 1) * 16);

    float acc[4][4][4] = {};

#define LDO(buf, k0) do { \
    uint32_t s0_ = sb + (buf) * OST_B; \
    _Pragma("unroll") \
    for (int p_ = 0; p_ < 8; p_++) { \
        int r_ = ldr + p_ * 16; \
        cp16(s0_ + (uint32_t)r_ * GSTR + ldc, \
             (const char*)(Ap + (size_t)r_ * K + (k0)) + ldc); \
    } \
    _Pragma("unroll") \
    for (int p_ = 0; p_ < 4; p_++) { \
        int r_ = ldr + p_ * 16; \
        cp16(s0_ + GTILE_B + (uint32_t)r_ * GSTR + ldc, \
             (const char*)(Bp + (size_t)r_ * K + (k0)) + ldc); \
    } \
    CP_COMMIT(); \
} while (0)

    LDO(0, 0);
    for (int ch = 0; ch < 64; ch++) {
        asm volatile("cp.async.wait_group 0;\n" ::: "memory");
        __syncthreads();
        if (ch + 1 < 64) LDO((ch + 1) & 1, (ch + 1) * 64);
        const uint32_t s0 = sb + (ch & 1) * OST_B;
        const uint32_t sA = s0, sB = s0 + GTILE_B;
#pragma unroll
        for (int k16 = 0; k16 < 4; k16++) {
            const uint32_t kadd = k16 * 32;
            uint32_t aa[4][4];
#pragma unroll
            for (int mb = 0; mb < 4; mb++)
                LDSM4(aa[mb], sA + a_off + mb * (16 * GSTR) + kadd);
#pragma unroll
            for (int jb = 0; jb < 2; jb++) {
                uint32_t bb[4];
                LDSM4(bb, sB + b_off + jb * (16 * GSTR) + kadd);
#pragma unroll
                for (int mb = 0; mb < 4; mb++) {
                    MMA16816(acc[mb][2 * jb], aa[mb], bb[0], bb[1]);
                    MMA16816(acc[mb][2 * jb + 1], aa[mb], bb[2], bb[3]);
                }
            }
        }
    }
#undef LDO

#pragma unroll
    for (int mb = 0; mb < 4; mb++) {
        const int mrow = row0 + wm * 64 + mb * 16 + (lane >> 2);
#pragma unroll
        for (int jf = 0; jf < 4; jf++) {
            const int col = col0 + wn * 32 + jf * 8 + (lane & 3) * 2;
            float2 lo2 = {acc[mb][jf][0], acc[mb][jf][1]};
            float2 hi2 = {acc[mb][jf][2], acc[mb][jf][3]};
            *(float2*)&C[(size_t)mrow * N + col] = lo2;
            *(float2*)&C[(size_t)(mrow + 8) * N + col] = hi2;
        }
    }
}

// ---------------- HMMA causal flash attention ----------------
// 128 q-rows x 128-key KV tiles. QK 1-term; PV 1-term.
// Raw-score softmax, lazy (warp-voted) rescale. 3-stage KV ring.
#define FSTR 272
#define KV_T2 (128 * FSTR)               /* 34816 */
#define KV_STAGE2 (2 * KV_T2)            /* 69632 */
#define FLASH_SMEM (3 * KV_STAGE2)       /* 208896 */

__global__ __launch_bounds__(256, 1) void flash_hmma(
    const __half* __restrict__ qh_g, const __half* __restrict__ kh_g,
    const __half* __restrict__ vh_g,
    __half* __restrict__ oh_g)
{
    extern __shared__ char dsm[];
    const uint32_t sq = smem_u32(dsm);
    const uint32_t sb = sq;
    const int tid = threadIdx.x, lane = tid & 31, w = tid >> 5;
    const int qt = (int)gridDim.x - 1 - (int)blockIdx.x;
    const int h = blockIdx.y, b = blockIdx.z;
    const int kvh = h >> 2;
    const int gr = qt * 128;
    const int nkt = qt + 1;

    {
        const __half* src = qh_g + ((size_t)(b * SEQ + gr)) * HID + h * 128;
#pragma unroll
        for (int i = 0; i < 8; i++) {
            int idx = tid + i * 256;
            int r = idx >> 4, c = idx & 15;
            cp16(sq + (uint32_t)r * FSTR + c * 16,
                 (const char*)(src + (size_t)r * HID) + c * 16);
        }
        CP_COMMIT();
        asm volatile("cp.async.wait_group 0;\n" ::: "memory");
        __syncthreads();
    }
    uint32_t qhf[8][4];
    {
        const uint32_t qoff = (uint32_t)(w * 16 + (lane & 15)) * FSTR + ((lane >> 4) * 16);
#pragma unroll
        for (int kf = 0; kf < 8; kf++)
            LDSM4(qhf[kf], sq + qoff + kf * 32);
    }
    __syncthreads();

    float o[16][4];
#pragma unroll
    for (int i = 0; i < 16; i++) { o[i][0] = 0.f; o[i][1] = 0.f; o[i][2] = 0.f; o[i][3] = 0.f; }
    float m0 = -1e5f, m1 = -1e5f, l0 = 0.f, l1 = 0.f;

    const uint32_t koff = (uint32_t)(((lane >> 4) << 3) + (lane & 7)) * FSTR + (((lane >> 3) & 1) * 16);
    const uint32_t voff = (uint32_t)((((lane >> 3) & 1) << 3) + (lane & 7)) * FSTR + ((lane >> 4) * 16);

    const __half* kh_p = kh_g + ((size_t)(b * SEQ)) * KVD + kvh * 128;
    const __half* vh_p = vh_g + ((size_t)(b * SEQ)) * KVD + kvh * 128;

#define LOADKV(kt_, buf_) do { \
    uint32_t s0_ = sb + (buf_) * KV_STAGE2; \
    const __half* gs_[2] = { \
        kh_p + (size_t)(kt_) * 128 * KVD, vh_p + (size_t)(kt_) * 128 * KVD}; \
    _Pragma("unroll") \
    for (int t_ = 0; t_ < 2; t_++) { \
        _Pragma("unroll") \
        for (int i_ = 0; i_ < 8; i_++) { \
            int idx_ = tid + i_ * 256; \
            int r_ = idx_ >> 4, c_ = idx_ & 15; \
            cp16(s0_ + t_ * KV_T2 + (uint32_t)r_ * FSTR + c_ * 16, \
                 (const char*)(gs_[t_] + (size_t)r_ * KVD) + c_ * 16); \
        } \
    } \
    CP_COMMIT(); \
} while (0)

    LOADKV(0, 0);
    if (nkt > 1) LOADKV(1, 1);
    const float Cs = 0.08838834764831845f * 1.4426950408889634f;

    int st = 0;
    int st2 = 2;
    for (int kt = 0; kt < nkt; kt++) {
        if (kt + 2 < nkt) {
            asm volatile("cp.async.wait_group 1;\n" ::: "memory");
        } else {
            asm volatile("cp.async.wait_group 0;\n" ::: "memory");
        }
        __syncthreads();
        if (kt + 2 < nkt) LOADKV(kt + 2, st2);

        const uint32_t sKh = sb + st * KV_STAGE2;
        const uint32_t sVh = sKh + KV_T2;

        // ---- QK^T (1-term, raw scores), 128 keys
        float s[16][4];
#pragma unroll
        for (int i = 0; i < 16; i++) { s[i][0] = 0.f; s[i][1] = 0.f; s[i][2] = 0.f; s[i][3] = 0.f; }
#pragma unroll
        for (int kf = 0; kf < 8; kf++) {
#pragma unroll
            for (int nb = 0; nb < 8; nb++) {
                uint32_t bh[4];
                LDSM4(bh, sKh + koff + nb * (16 * FSTR) + kf * 32);
                MMA16816(s[2 * nb], qhf[kf], bh[0], bh[1]);
                MMA16816(s[2 * nb + 1], qhf[kf], bh[2], bh[3]);
            }
        }
        // ---- causal mask (diagonal 128x128 tile only)
        if (kt == nkt - 1) {
            const int r0 = gr + w * 16 + (lane >> 2);
            const int c0 = kt * 128 + 2 * (lane & 3);
#pragma unroll
            for (int nf = 0; nf < 16; nf++) {
#pragma unroll
                for (int j = 0; j < 4; j++) {
                    int col = c0 + nf * 8 + (j & 1);
                    int row = r0 + (j >> 1) * 8;
                    if (col > row) s[nf][j] = -1e5f;
                }
            }
        }
        // ---- online softmax: lazy rescale with warp vote
        float mx0 = -1e30f, mx1 = -1e30f;
#pragma unroll
        for (int nf = 0; nf < 16; nf++) {
            mx0 = fmaxf(mx0, fmaxf(s[nf][0], s[nf][1]));
            mx1 = fmaxf(mx1, fmaxf(s[nf][2], s[nf][3]));
        }
        mx0 = fmaxf(mx0, __shfl_xor_sync(0xffffffffu, mx0, 1));
        mx0 = fmaxf(mx0, __shfl_xor_sync(0xffffffffu, mx0, 2));
        mx1 = fmaxf(mx1, __shfl_xor_sync(0xffffffffu, mx1, 1));
        mx1 = fmaxf(mx1, __shfl_xor_sync(0xffffffffu, mx1, 2));
        if (__any_sync(0xffffffffu, (mx0 > m0) || (mx1 > m1))) {
            const float mn0 = fmaxf(m0, mx0), mn1 = fmaxf(m1, mx1);
            const float cr0 = exp2p((m0 - mn0) * Cs), cr1 = exp2p((m1 - mn1) * Cs);
            m0 = mn0; m1 = mn1;
            l0 *= cr0; l1 *= cr1;
#pragma unroll
            for (int nf = 0; nf < 16; nf++) {
                o[nf][0] *= cr0; o[nf][1] *= cr0; o[nf][2] *= cr1; o[nf][3] *= cr1;
            }
        }
        const float c0_ = -m0 * Cs, c1_ = -m1 * Cs;
        float rs0 = 0.f, rs1 = 0.f;
#pragma unroll
        for (int nf = 0; nf < 16; nf++) {
            float p0 = exp2p(fmaf(s[nf][0], Cs, c0_));
            float p1 = exp2p(fmaf(s[nf][1], Cs, c0_));
            float p2 = exp2p(fmaf(s[nf][2], Cs, c1_));
            float p3 = exp2p(fmaf(s[nf][3], Cs, c1_));
            s[nf][0] = p0; s[nf][1] = p1; s[nf][2] = p2; s[nf][3] = p3;
            rs0 += p0 + p1; rs1 += p2 + p3;
        }
        rs0 += __shfl_xor_sync(0xffffffffu, rs0, 1);
        rs0 += __shfl_xor_sync(0xffffffffu, rs0, 2);
        rs1 += __shfl_xor_sync(0xffffffffu, rs1, 1);
        rs1 += __shfl_xor_sync(0xffffffffu, rs1, 2);
        l0 += rs0;
        l1 += rs1;
        // ---- P @ V (1-term)
#pragma unroll
        for (int kb = 0; kb < 8; kb++) {
            uint32_t ph[4];
            ph[0] = pack_f16x2(s[2 * kb][1], s[2 * kb][0]);
            ph[1] = pack_f16x2(s[2 * kb][3], s[2 * kb][2]);
            ph[2] = pack_f16x2(s[2 * kb + 1][1], s[2 * kb + 1][0]);
            ph[3] = pack_f16x2(s[2 * kb + 1][3], s[2 * kb + 1][2]);
#pragma unroll
            for (int ng = 0; ng < 8; ng++) {
                uint32_t vv[4];
                LDSM4T(vv, sVh + voff + kb * (16 * FSTR) + ng * 32);
                MMA16816(o[2 * ng], ph, vv[0], vv[1]);
                MMA16816(o[2 * ng + 1], ph, vv[2], vv[3]);
            }
        }
        st = (st == 2) ? 0 : st + 1;
        st2 = (st2 == 2) ? 0 : st2 + 1;
    }
#undef LOADKV

    const float inv0 = 1.f / l0, inv1 = 1.f / l1;
    const size_t row0_ = (size_t)(b * SEQ + gr + w * 16 + (lane >> 2));
    const int colb = h * 128 + 2 * (lane & 3);
#pragma unroll
    for (int nf = 0; nf < 16; nf++) {
        const int col = colb + nf * 8;
        uint32_t h01 = pack_f16x2(o[nf][1] * inv0, o[nf][0] * inv0);
        uint32_t h23 = pack_f16x2(o[nf][3] * inv1, o[nf][2] * inv1);
        *(uint32_t*)&oh_g[row0_ * HID + col] = h01;
        *(uint32_t*)&oh_g[(row0_ + 8) * HID + col] = h23;
    }
}

// ---------------- launch ----------------
extern "C" void kernel_launch(void* const* d_in, const int* in_sizes, int n_in,
                              void* d_out, int out_size)
{
    const float* x  = (const float*)d_in[0];
    const float* Wq = (const float*)d_in[2];
    const float* Aq = (const float*)d_in[3];
    const float* Bq = (const float*)d_in[4];
    const float* mq = (const float*)d_in[5];
    const float* Wk = (const float*)d_in[6];
    const float* Ak = (const float*)d_in[7];
    const float* Bk = (const float*)d_in[8];
    const float* mk = (const float*)d_in[9];
    const float* Wv = (const float*)d_in[10];
    const float* Av = (const float*)d_in[11];
    const float* Bv = (const float*)d_in[12];
    const float* mv = (const float*)d_in[13];
    const float* Wo = (const float*)d_in[14];
    const float* Ao = (const float*)d_in[15];
    const float* Bo = (const float*)d_in[16];
    const float* mo = (const float*)d_in[17];

    __half *xh, *xl, *Wqh, *Wkh, *Wvh, *Woh;
    __half *qh, *kh, *vh, *ath;
    cudaGetSymbolAddress((void**)&xh, g_xh);   cudaGetSymbolAddress((void**)&xl, g_xl);
    cudaGetSymbolAddress((void**)&Wqh, g_Wqh); cudaGetSymbolAddress((void**)&Wkh, g_Wkh);
    cudaGetSymbolAddress((void**)&Wvh, g_Wvh); cudaGetSymbolAddress((void**)&Woh, g_Woh);
    cudaGetSymbolAddress((void**)&qh, g_qh);   cudaGetSymbolAddress((void**)&kh, g_kh);
    cudaGetSymbolAddress((void**)&vh, g_vh);
    cudaGetSymbolAddress((void**)&ath, g_ath);

    cudaFuncSetAttribute(gemm_qkv, cudaFuncAttributeMaxDynamicSharedMemorySize, QKV_SMEM);
    cudaFuncSetAttribute(gemm_o, cudaFuncAttributeMaxDynamicSharedMemorySize, GO_SMEM);
    cudaFuncSetAttribute(flash_hmma, cudaFuncAttributeMaxDynamicSharedMemorySize, FLASH_SMEM);

    // 1) DoRA effective weights + x split (one fused launch)
    const int split_blocks = (TOK * HID / 4 + 255) / 256;
    dora_split<<<10240 + split_blocks, 256>>>(
        Wq, Aq, Bq, mq, Wk, Ak, Bk, mk, Wv, Av, Bv, mv, Wo, Ao, Bo, mo,
        Wqh, Wkh, Wvh, Woh, x, xh, xl);

    // 2) merged q/k/v projections (K/V as K=8192 1-term, Q as K=4096 1-term)
    gemm_qkv<<<dim3(48, TOK / 128), 128, QKV_SMEM>>>(
        xh, xl, Wqh, Wkh, Wvh, qh, kh, vh);

    // 3) causal attention (HMMA, 128-key tiles) -> single fp16 output
    flash_hmma<<<dim3(SEQ / 128, 32, 2), 256, FLASH_SMEM>>>(qh, kh, vh, ath);

    // 4) output projection (1-term, 128x64 tiles) -> d_out (fp32)
    gemm_o<<<dim3(HID / 64, TOK / 128), 128, GO_SMEM>>>(ath, Woh, (float*)d_out);
}

// round 17
// speedup vs baseline: 1.5060x; 1.5060x over previous
#include <cuda_runtime.h>
#include <cuda_fp16.h>
#include <cstdint>
#include <math.h>

#define HID 4096
#define KVD 1024
#define TOK 4096   /* B*S */
#define SEQ 2048

// ---------------- device scratch ----------------
__device__ __half g_xh[TOK * HID];
__device__ __half g_xl[TOK * HID];
__device__ __half g_Wqh[HID * HID];
__device__ __half g_Wkh[KVD * HID];
__device__ __half g_Wvh[KVD * HID];
__device__ __half g_Woh[HID * HID];
__device__ __half g_qh[TOK * HID];
__device__ __half g_kh[TOK * KVD];
__device__ __half g_vh[TOK * KVD];
__device__ __half g_ath[TOK * HID];

// ---------------- helpers ----------------
__device__ __forceinline__ uint32_t smem_u32(const void* p) {
    uint32_t a;
    asm("{ .reg .u64 t; cvta.to.shared.u64 t, %1; cvt.u32.u64 %0, t; }" : "=r"(a) : "l"(p));
    return a;
}
__device__ __forceinline__ void cp16(uint32_t dst, const void* src) {
    asm volatile("cp.async.cg.shared.global [%0], [%1], 16;\n" :: "r"(dst), "l"(src) : "memory");
}
#define CP_COMMIT() asm volatile("cp.async.commit_group;\n" ::: "memory")

#define LDSM4(r, a) \
    asm volatile("ldmatrix.sync.aligned.m8n8.x4.shared.b16 {%0,%1,%2,%3}, [%4];" \
                 : "=r"((r)[0]), "=r"((r)[1]), "=r"((r)[2]), "=r"((r)[3]) : "r"(a))
#define LDSM4T(r, a) \
    asm volatile("ldmatrix.sync.aligned.m8n8.x4.trans.shared.b16 {%0,%1,%2,%3}, [%4];" \
                 : "=r"((r)[0]), "=r"((r)[1]), "=r"((r)[2]), "=r"((r)[3]) : "r"(a))

#define MMA16816(d, a, b0, b1) \
    asm volatile("mma.sync.aligned.m16n8k16.row.col.f32.f16.f16.f32 " \
                 "{%0,%1,%2,%3}, {%4,%5,%6,%7}, {%8,%9}, {%0,%1,%2,%3};" \
                 : "+f"((d)[0]), "+f"((d)[1]), "+f"((d)[2]), "+f"((d)[3]) \
                 : "r"((a)[0]), "r"((a)[1]), "r"((a)[2]), "r"((a)[3]), "r"(b0), "r"(b1))

__device__ __forceinline__ uint32_t pack_f16x2(float hi_, float lo_) {
    __half2 h = __floats2half2_rn(lo_, hi_);
    return *(uint32_t*)&h;
}
// fast exp2 on FMA pipe (no MUFU). rel err ~2.4e-6.
__device__ __forceinline__ float exp2p(float x) {
    x = fmaxf(x, -120.f);
    int e = __float2int_rn(x);
    float f = x - (float)e;
    float p = 1.3333558e-3f;
    p = fmaf(p, f, 9.6181291e-3f);
    p = fmaf(p, f, 5.5504109e-2f);
    p = fmaf(p, f, 2.4022651e-1f);
    p = fmaf(p, f, 6.9314718e-1f);
    p = fmaf(p, f, 1.0f);
    return p * __int_as_float((uint32_t)(e + 127) << 23);
}

// -------- fused: DoRA weights (blocks 0..10239) + x split (blocks 10240..) --
__global__ __launch_bounds__(256) void dora_split(
    const float* __restrict__ Wq, const float* __restrict__ Aq,
    const float* __restrict__ Bq, const float* __restrict__ mq,
    const float* __restrict__ Wk, const float* __restrict__ Ak,
    const float* __restrict__ Bk, const float* __restrict__ mk,
    const float* __restrict__ Wv, const float* __restrict__ Av,
    const float* __restrict__ Bv, const float* __restrict__ mv,
    const float* __restrict__ Wo, const float* __restrict__ Ao,
    const float* __restrict__ Bo, const float* __restrict__ mo,
    __half* __restrict__ Wqh, __half* __restrict__ Wkh,
    __half* __restrict__ Wvh, __half* __restrict__ Woh,
    const float* __restrict__ x, __half* __restrict__ xh,
    __half* __restrict__ xl)
{
    const int bx = blockIdx.x;
    const int tid = threadIdx.x;

    if (bx >= 10240) {
        int i = (bx - 10240) * 256 + tid;
        if (i < TOK * HID / 4) {
            float4 v = ((const float4*)x)[i];
            float vv[4] = {v.x, v.y, v.z, v.w};
            size_t base = (size_t)i * 4;
#pragma unroll
            for (int e = 0; e < 4; e++) {
                __half h = __float2half_rn(vv[e]);
                xh[base + e] = h;
                xl[base + e] = __float2half_rn(vv[e] - __half2float(h));
            }
        }
        return;
    }

    const float *W, *A, *Bm, *mvec;
    __half *Whi;
    int row;
    if (bx < 4096)      { W = Wq; A = Aq; Bm = Bq; mvec = mq; Whi = Wqh; row = bx; }
    else if (bx < 5120) { W = Wk; A = Ak; Bm = Bk; mvec = mk; Whi = Wkh; row = bx - 4096; }
    else if (bx < 6144) { W = Wv; A = Av; Bm = Bv; mvec = mv; Whi = Wvh; row = bx - 5120; }
    else                { W = Wo; A = Ao; Bm = Bo; mvec = mo; Whi = Woh; row = bx - 6144; }

    float b[8];
#pragma unroll
    for (int r = 0; r < 8; r++) b[r] = 2.0f * Bm[row * 8 + r];

    const float4* Wrow = (const float4*)(W + (size_t)row * HID);
    float4 w[4];
    float ss = 0.f;
#pragma unroll
    for (int c = 0; c < 4; c++) {
        int col4 = tid + 256 * c;
        float4 wv = Wrow[col4];
#pragma unroll
        for (int r = 0; r < 8; r++) {
            float4 av = ((const float4*)(A + (size_t)r * HID))[col4];
            wv.x += b[r] * av.x; wv.y += b[r] * av.y;
            wv.z += b[r] * av.z; wv.w += b[r] * av.w;
        }
        ss += wv.x * wv.x + wv.y * wv.y + wv.z * wv.z + wv.w * wv.w;
        w[c] = wv;
    }
#pragma unroll
    for (int off = 16; off; off >>= 1)
        ss += __shfl_xor_sync(0xffffffffu, ss, off);

    __shared__ float red[8];
    __shared__ float s_scale;
    if ((tid & 31) == 0) red[tid >> 5] = ss;
    __syncthreads();
    if (tid == 0) {
        float t = 0.f;
#pragma unroll
        for (int i = 0; i < 8; i++) t += red[i];
        s_scale = mvec[row] / (sqrtf(t) + 1e-8f);
    }
    __syncthreads();
    const float sc = s_scale;
#pragma unroll
    for (int c = 0; c < 4; c++) {
        float vv[4] = {w[c].x * sc, w[c].y * sc, w[c].z * sc, w[c].w * sc};
        size_t base = (size_t)row * HID + (tid + 256 * c) * 4;
        __half2 p0 = __floats2half2_rn(vv[0], vv[1]);
        __half2 p1 = __floats2half2_rn(vv[2], vv[3]);
        *(__half2*)&Whi[base] = p0;
        *(__half2*)&Whi[base + 2] = p1;
    }
}

// ======= GEMM mainloop: 128x128 CTA tile, 128 threads, K-chunk 64 =======
#define GSTR 144
#define GTILE_B (128 * GSTR)             /* 18432 */
#define QKV_STAGE (2 * GTILE_B)          /* 36864 */
#define QKV_SMEM (2 * QKV_STAGE)         /* 73728 -> 3 CTAs/SM */
#define PGRID 444                        /* persistent grid: 3 * 148 */

__device__ __forceinline__ void hmma_loop64(
    uint32_t sb, const __half* A0, const __half* A1, const __half* Bp,
    int nch, int tid, float acc[4][8][4])
{
    const int lane = tid & 31, wid = tid >> 5;
    const int wm = wid & 1, wn = wid >> 1;
    const int K = 4096;
    const int ldr = tid >> 3;
    const int ldc = (tid & 7) * 16;

    const uint32_t a_off = (uint32_t)(wm * 64 + (lane & 15)) * GSTR + ((lane >> 4) * 16);
    const uint32_t b_off = (uint32_t)(wn * 64 + (((lane >> 4) << 3) + (lane & 7))) * GSTR
                           + (((lane >> 3) & 1) * 16);

#define LD64(buf, ch_) do { \
    uint32_t s0_ = sb + (buf) * QKV_STAGE; \
    const __half* a_ = ((ch_) < 64 ? A0 : A1) + ((ch_) & 63) * 64; \
    const __half* b_ = Bp + ((ch_) & 63) * 64; \
    const __half* gg_[2] = {a_, b_}; \
    _Pragma("unroll") \
    for (int t_ = 0; t_ < 2; t_++) { \
        uint32_t st_ = s0_ + t_ * GTILE_B; \
        _Pragma("unroll") \
        for (int p_ = 0; p_ < 8; p_++) { \
            int r_ = ldr + p_ * 16; \
            cp16(st_ + (uint32_t)r_ * GSTR + ldc, \
                 (const char*)(gg_[t_] + (size_t)r_ * K) + ldc); \
        } \
    } \
    CP_COMMIT(); \
} while (0)

    LD64(0, 0);
    for (int ch = 0; ch < nch; ch++) {
        asm volatile("cp.async.wait_group 0;\n" ::: "memory");
        __syncthreads();
        if (ch + 1 < nch) LD64((ch + 1) & 1, ch + 1);
        const uint32_t s0 = sb + (ch & 1) * QKV_STAGE;
        const uint32_t sA = s0, sB = s0 + GTILE_B;
#pragma unroll
        for (int k16 = 0; k16 < 4; k16++) {
            const uint32_t kadd = k16 * 32;
            uint32_t aa[4][4];
#pragma unroll
            for (int mb = 0; mb < 4; mb++)
                LDSM4(aa[mb], sA + a_off + mb * (16 * GSTR) + kadd);
#pragma unroll
            for (int jb = 0; jb < 4; jb++) {
                uint32_t bb[4];
                LDSM4(bb, sB + b_off + jb * (16 * GSTR) + kadd);
#pragma unroll
                for (int mb = 0; mb < 4; mb++) {
                    MMA16816(acc[mb][2 * jb], aa[mb], bb[0], bb[1]);
                    MMA16816(acc[mb][2 * jb + 1], aa[mb], bb[2], bb[3]);
                }
            }
        }
    }
#undef LD64
}

// ---------------- merged QKV projection (persistent) ----------------
// tile t: tx = t%48 (0..7 K, 8..15 V, 16..47 Q), ty = t/48 (M tile).
__global__ __launch_bounds__(128, 3) void gemm_qkv(
    const __half* __restrict__ xh, const __half* __restrict__ xl,
    const __half* __restrict__ Wqh, const __half* __restrict__ Wkh,
    const __half* __restrict__ Wvh,
    __half* __restrict__ qh, __half* __restrict__ kh, __half* __restrict__ vh)
{
    extern __shared__ char dsm[];
    const uint32_t sb = smem_u32(dsm);
    const int tid = threadIdx.x, lane = tid & 31, wid = tid >> 5;
    const int wm = wid & 1, wn = wid >> 1;
    const int K = 4096;

    for (int t = blockIdx.x; t < 48 * 32; t += PGRID) {
        const int tx = t % 48;
        const int row0 = (t / 48) << 7;

        const __half* Bp;
        __half* Oh;
        int N, col0, nch;
        if (tx < 8)       { Bp = Wkh; Oh = kh; N = KVD; col0 = tx << 7; nch = 128; }
        else if (tx < 16) { Bp = Wvh; Oh = vh; N = KVD; col0 = (tx - 8) << 7; nch = 128; }
        else              { Bp = Wqh; Oh = qh; N = HID; col0 = (tx - 16) << 7; nch = 64; }

        float acc[4][8][4] = {};
        hmma_loop64(sb, xh + (size_t)row0 * K, xl + (size_t)row0 * K,
                    Bp + (size_t)col0 * K, nch, tid, acc);

#pragma unroll
        for (int mb = 0; mb < 4; mb++) {
            const int mrow = row0 + wm * 64 + mb * 16 + (lane >> 2);
#pragma unroll
            for (int jf = 0; jf < 8; jf++) {
                const int col = col0 + wn * 64 + jf * 8 + (lane & 3) * 2;
                uint32_t h01 = pack_f16x2(acc[mb][jf][1], acc[mb][jf][0]);
                uint32_t h23 = pack_f16x2(acc[mb][jf][3], acc[mb][jf][2]);
                *(uint32_t*)&Oh[(size_t)mrow * N + col] = h01;
                *(uint32_t*)&Oh[(size_t)(mrow + 8) * N + col] = h23;
            }
        }
        __syncthreads();
    }
}

// ---------------- output projection (persistent, 1-term, fp32 out) ---------
__global__ __launch_bounds__(128, 3) void gemm_o(
    const __half* __restrict__ Ah, const __half* __restrict__ Bh,
    float* __restrict__ C)
{
    extern __shared__ char dsm[];
    const uint32_t sb = smem_u32(dsm);
    const int tid = threadIdx.x, lane = tid & 31, wid = tid >> 5;
    const int wm = wid & 1, wn = wid >> 1;
    const int K = 4096, N = HID;

    for (int t = blockIdx.x; t < 32 * 32; t += PGRID) {
        const int row0 = (t >> 5) << 7, col0 = (t & 31) << 7;

        float acc[4][8][4] = {};
        hmma_loop64(sb, Ah + (size_t)row0 * K, Ah + (size_t)row0 * K,
                    Bh + (size_t)col0 * K, 64, tid, acc);

#pragma unroll
        for (int mb = 0; mb < 4; mb++) {
            const int mrow = row0 + wm * 64 + mb * 16 + (lane >> 2);
#pragma unroll
            for (int jf = 0; jf < 8; jf++) {
                const int col = col0 + wn * 64 + jf * 8 + (lane & 3) * 2;
                float2 lo2 = {acc[mb][jf][0], acc[mb][jf][1]};
                float2 hi2 = {acc[mb][jf][2], acc[mb][jf][3]};
                *(float2*)&C[(size_t)mrow * N + col] = lo2;
                *(float2*)&C[(size_t)(mrow + 8) * N + col] = hi2;
            }
        }
        __syncthreads();
    }
}

// ---------------- HMMA causal flash attention ----------------
// QK 1-term; PV 1-term. Raw-score softmax, lazy (warp-voted) rescale.
#define FSTR 272
#define KV_T 17408
#define KV_STAGE (2 * KV_T)
#define FLASH_SMEM (3 * KV_STAGE)

__global__ __launch_bounds__(256, 1) void flash_hmma(
    const __half* __restrict__ qh_g, const __half* __restrict__ kh_g,
    const __half* __restrict__ vh_g,
    __half* __restrict__ oh_g)
{
    extern __shared__ char dsm[];
    const uint32_t sq = smem_u32(dsm);
    const uint32_t sb = sq;
    const int tid = threadIdx.x, lane = tid & 31, w = tid >> 5;
    const int qt = (int)gridDim.x - 1 - (int)blockIdx.x;
    const int h = blockIdx.y, b = blockIdx.z;
    const int kvh = h >> 2;
    const int gr = qt * 128;
    const int nkt = 2 * qt + 2;

    {
        const __half* src = qh_g + ((size_t)(b * SEQ + gr)) * HID + h * 128;
#pragma unroll
        for (int i = 0; i < 8; i++) {
            int idx = tid + i * 256;
            int r = idx >> 4, c = idx & 15;
            cp16(sq + (uint32_t)r * FSTR + c * 16,
                 (const char*)(src + (size_t)r * HID) + c * 16);
        }
        CP_COMMIT();
        asm volatile("cp.async.wait_group 0;\n" ::: "memory");
        __syncthreads();
    }
    uint32_t qhf[8][4];
    {
        const uint32_t qoff = (uint32_t)(w * 16 + (lane & 15)) * FSTR + ((lane >> 4) * 16);
#pragma unroll
        for (int kf = 0; kf < 8; kf++)
            LDSM4(qhf[kf], sq + qoff + kf * 32);
    }
    __syncthreads();

    float o[16][4];
#pragma unroll
    for (int i = 0; i < 16; i++) { o[i][0] = 0.f; o[i][1] = 0.f; o[i][2] = 0.f; o[i][3] = 0.f; }
    float m0 = -1e5f, m1 = -1e5f, l0 = 0.f, l1 = 0.f;

    const uint32_t koff = (uint32_t)(((lane >> 4) << 3) + (lane & 7)) * FSTR + (((lane >> 3) & 1) * 16);
    const uint32_t voff = (uint32_t)((((lane >> 3) & 1) << 3) + (lane & 7)) * FSTR + ((lane >> 4) * 16);

    const __half* kh_p = kh_g + ((size_t)(b * SEQ)) * KVD + kvh * 128;
    const __half* vh_p = vh_g + ((size_t)(b * SEQ)) * KVD + kvh * 128;

#define LOADKV(kt_, buf_) do { \
    uint32_t s0_ = sb + (buf_) * KV_STAGE; \
    const __half* gs_[2] = { \
        kh_p + (size_t)(kt_) * 64 * KVD, vh_p + (size_t)(kt_) * 64 * KVD}; \
    _Pragma("unroll") \
    for (int t_ = 0; t_ < 2; t_++) { \
        _Pragma("unroll") \
        for (int i_ = 0; i_ < 4; i_++) { \
            int idx_ = tid + i_ * 256; \
            int r_ = idx_ >> 4, c_ = idx_ & 15; \
            cp16(s0_ + t_ * KV_T + (uint32_t)r_ * FSTR + c_ * 16, \
                 (const char*)(gs_[t_] + (size_t)r_ * KVD) + c_ * 16); \
        } \
    } \
    CP_COMMIT(); \
} while (0)

    LOADKV(0, 0);
    LOADKV(1, 1);
    const float Cs = 0.08838834764831845f * 1.4426950408889634f;

    int st = 0;
    int st2 = 2;
    for (int kt = 0; kt < nkt; kt++) {
        if (kt + 2 < nkt) {
            asm volatile("cp.async.wait_group 1;\n" ::: "memory");
        } else {
            asm volatile("cp.async.wait_group 0;\n" ::: "memory");
        }
        __syncthreads();
        if (kt + 2 < nkt) LOADKV(kt + 2, st2);

        const uint32_t sKh = sb + st * KV_STAGE;
        const uint32_t sVh = sKh + KV_T;

        float s[8][4];
#pragma unroll
        for (int i = 0; i < 8; i++) { s[i][0] = 0.f; s[i][1] = 0.f; s[i][2] = 0.f; s[i][3] = 0.f; }
#pragma unroll
        for (int kf = 0; kf < 8; kf++) {
#pragma unroll
            for (int nb = 0; nb < 4; nb++) {
                uint32_t bh[4];
                LDSM4(bh, sKh + koff + nb * (16 * FSTR) + kf * 32);
                MMA16816(s[2 * nb], qhf[kf], bh[0], bh[1]);
                MMA16816(s[2 * nb + 1], qhf[kf], bh[2], bh[3]);
            }
        }
        if (kt >= nkt - 2) {
            const int r0 = gr + w * 16 + (lane >> 2);
            const int c0 = kt * 64 + 2 * (lane & 3);
#pragma unroll
            for (int nf = 0; nf < 8; nf++) {
#pragma unroll
                for (int j = 0; j < 4; j++) {
                    int col = c0 + nf * 8 + (j & 1);
                    int row = r0 + (j >> 1) * 8;
                    if (col > row) s[nf][j] = -1e5f;
                }
            }
        }
        float mx0 = -1e30f, mx1 = -1e30f;
#pragma unroll
        for (int nf = 0; nf < 8; nf++) {
            mx0 = fmaxf(mx0, fmaxf(s[nf][0], s[nf][1]));
            mx1 = fmaxf(mx1, fmaxf(s[nf][2], s[nf][3]));
        }
        mx0 = fmaxf(mx0, __shfl_xor_sync(0xffffffffu, mx0, 1));
        mx0 = fmaxf(mx0, __shfl_xor_sync(0xffffffffu, mx0, 2));
        mx1 = fmaxf(mx1, __shfl_xor_sync(0xffffffffu, mx1, 1));
        mx1 = fmaxf(mx1, __shfl_xor_sync(0xffffffffu, mx1, 2));
        if (__any_sync(0xffffffffu, (mx0 > m0) || (mx1 > m1))) {
            const float mn0 = fmaxf(m0, mx0), mn1 = fmaxf(m1, mx1);
            const float cr0 = exp2p((m0 - mn0) * Cs), cr1 = exp2p((m1 - mn1) * Cs);
            m0 = mn0; m1 = mn1;
            l0 *= cr0; l1 *= cr1;
#pragma unroll
            for (int nf = 0; nf < 16; nf++) {
                o[nf][0] *= cr0; o[nf][1] *= cr0; o[nf][2] *= cr1; o[nf][3] *= cr1;
            }
        }
        const float c0_ = -m0 * Cs, c1_ = -m1 * Cs;
        float rs0 = 0.f, rs1 = 0.f;
#pragma unroll
        for (int nf = 0; nf < 8; nf++) {
            float p0 = exp2p(fmaf(s[nf][0], Cs, c0_));
            float p1 = exp2p(fmaf(s[nf][1], Cs, c0_));
            float p2 = exp2p(fmaf(s[nf][2], Cs, c1_));
            float p3 = exp2p(fmaf(s[nf][3], Cs, c1_));
            s[nf][0] = p0; s[nf][1] = p1; s[nf][2] = p2; s[nf][3] = p3;
            rs0 += p0 + p1; rs1 += p2 + p3;
        }
        rs0 += __shfl_xor_sync(0xffffffffu, rs0, 1);
        rs0 += __shfl_xor_sync(0xffffffffu, rs0, 2);
        rs1 += __shfl_xor_sync(0xffffffffu, rs1, 1);
        rs1 += __shfl_xor_sync(0xffffffffu, rs1, 2);
        l0 += rs0;
        l1 += rs1;
#pragma unroll
        for (int kb = 0; kb < 4; kb++) {
            uint32_t ph[4];
#pragma unroll
            for (int q2 = 0; q2 < 2; q2++) {
                const int nf = 2 * kb + q2;
                ph[2 * q2]     = pack_f16x2(s[nf][1], s[nf][0]);
                ph[2 * q2 + 1] = pack_f16x2(s[nf][3], s[nf][2]);
            }
#pragma unroll
            for (int ng = 0; ng < 8; ng++) {
                uint32_t vv[4];
                LDSM4T(vv, sVh + voff + kb * (16 * FSTR) + ng * 32);
                MMA16816(o[2 * ng], ph, vv[0], vv[1]);
                MMA16816(o[2 * ng + 1], ph, vv[2], vv[3]);
            }
        }
        st = (st == 2) ? 0 : st + 1;
        st2 = (st2 == 2) ? 0 : st2 + 1;
    }
#undef LOADKV

    const float inv0 = 1.f / l0, inv1 = 1.f / l1;
    const size_t row0_ = (size_t)(b * SEQ + gr + w * 16 + (lane >> 2));
    const int colb = h * 128 + 2 * (lane & 3);
#pragma unroll
    for (int nf = 0; nf < 16; nf++) {
        const int col = colb + nf * 8;
        uint32_t h01 = pack_f16x2(o[nf][1] * inv0, o[nf][0] * inv0);
        uint32_t h23 = pack_f16x2(o[nf][3] * inv1, o[nf][2] * inv1);
        *(uint32_t*)&oh_g[row0_ * HID + col] = h01;
        *(uint32_t*)&oh_g[(row0_ + 8) * HID + col] = h23;
    }
}

// ---------------- launch ----------------
extern "C" void kernel_launch(void* const* d_in, const int* in_sizes, int n_in,
                              void* d_out, int out_size)
{
    const float* x  = (const float*)d_in[0];
    const float* Wq = (const float*)d_in[2];
    const float* Aq = (const float*)d_in[3];
    const float* Bq = (const float*)d_in[4];
    const float* mq = (const float*)d_in[5];
    const float* Wk = (const float*)d_in[6];
    const float* Ak = (const float*)d_in[7];
    const float* Bk = (const float*)d_in[8];
    const float* mk = (const float*)d_in[9];
    const float* Wv = (const float*)d_in[10];
    const float* Av = (const float*)d_in[11];
    const float* Bv = (const float*)d_in[12];
    const float* mv = (const float*)d_in[13];
    const float* Wo = (const float*)d_in[14];
    const float* Ao = (const float*)d_in[15];
    const float* Bo = (const float*)d_in[16];
    const float* mo = (const float*)d_in[17];

    __half *xh, *xl, *Wqh, *Wkh, *Wvh, *Woh;
    __half *qh, *kh, *vh, *ath;
    cudaGetSymbolAddress((void**)&xh, g_xh);   cudaGetSymbolAddress((void**)&xl, g_xl);
    cudaGetSymbolAddress((void**)&Wqh, g_Wqh); cudaGetSymbolAddress((void**)&Wkh, g_Wkh);
    cudaGetSymbolAddress((void**)&Wvh, g_Wvh); cudaGetSymbolAddress((void**)&Woh, g_Woh);
    cudaGetSymbolAddress((void**)&qh, g_qh);   cudaGetSymbolAddress((void**)&kh, g_kh);
    cudaGetSymbolAddress((void**)&vh, g_vh);
    cudaGetSymbolAddress((void**)&ath, g_ath);

    cudaFuncSetAttribute(gemm_qkv, cudaFuncAttributeMaxDynamicSharedMemorySize, QKV_SMEM);
    cudaFuncSetAttribute(gemm_o, cudaFuncAttributeMaxDynamicSharedMemorySize, QKV_SMEM);
    cudaFuncSetAttribute(flash_hmma, cudaFuncAttributeMaxDynamicSharedMemorySize, FLASH_SMEM);

    // 1) DoRA effective weights + x split (one fused launch)
    const int split_blocks = (TOK * HID / 4 + 255) / 256;
    dora_split<<<10240 + split_blocks, 256>>>(
        Wq, Aq, Bq, mq, Wk, Ak, Bk, mk, Wv, Av, Bv, mv, Wo, Ao, Bo, mo,
        Wqh, Wkh, Wvh, Woh, x, xh, xl);

    // 2) merged q/k/v projections (persistent grid)
    gemm_qkv<<<PGRID, 128, QKV_SMEM>>>(xh, xl, Wqh, Wkh, Wvh, qh, kh, vh);

    // 3) causal attention (HMMA, 64-key tiles) -> single fp16 output
    flash_hmma<<<dim3(SEQ / 128, 32, 2), 256, FLASH_SMEM>>>(qh, kh, vh, ath);

    // 4) output projection (persistent grid, 1-term) -> d_out (fp32)
    gemm_o<<<PGRID, 128, QKV_SMEM>>>(ath, Woh, (float*)d_out);
}